// round 4
// baseline (speedup 1.0000x reference)
#include <cuda_runtime.h>
#include <cuda_fp16.h>
#include <math.h>

#define NN 8192
#define DD 256
#define HH 64

// Pre-scaled features: he[j, d] = e_j * h[j, d], fp16 (4 MB, L2-resident).
__device__ __half g_he[NN * DD];

// ---------------------------------------------------------------------------
// Kernel 1: MLP gate + he emission.
// 16 rows/block (512 blocks), 256 thr = 16 rows x 16 jg(x4 hidden).
// W1 staged in smem in 32KB halves [k][j] (conflict-light float4-over-j LDS);
// h via __ldg float4 (16-way broadcast). FMA-bound by construction.
// ---------------------------------------------------------------------------
#define MLP_ROWS 16
__global__ void __launch_bounds__(256) mlp_kernel(
    const float* __restrict__ h, const float* __restrict__ W1,
    const float* __restrict__ b1, const float* __restrict__ W2,
    const float* __restrict__ b2, float* __restrict__ out_e) {

  __shared__ float sW[128 * HH];          // one K-half of W1: 32 KB
  __shared__ float sPart[MLP_ROWS][17];
  __shared__ float sE[MLP_ROWS];

  const int tid = threadIdx.x;
  const int rg = tid >> 4;                 // 0..15 -> local row
  const int jg = tid & 15;                 // 0..15
  const int j0 = jg * 4;
  const int rowbase = blockIdx.x * MLP_ROWS;
  const int row = rowbase + rg;

  float acc0 = __ldg(&b1[j0]),     acc1 = __ldg(&b1[j0 + 1]);
  float acc2 = __ldg(&b1[j0 + 2]), acc3 = __ldg(&b1[j0 + 3]);

  const float4* hrow = (const float4*)(h + (size_t)row * DD);
  const float4* sW4 = (const float4*)sW;
  const float4* W14 = (const float4*)W1;

  for (int half = 0; half < 2; half++) {
    __syncthreads();
    // Stage W1[k in half*128 .. +128][0..63] -> sW (identity copy, float4).
    #pragma unroll
    for (int i = tid; i < 128 * HH / 4; i += 256)
      ((float4*)sW)[i] = __ldg(&W14[half * (128 * HH / 4) + i]);
    __syncthreads();

    #pragma unroll 4
    for (int k4 = 0; k4 < 32; k4++) {
      const float4 hv = __ldg(&hrow[half * 32 + k4]);
      const float4 wA = sW4[(k4 * 4 + 0) * 16 + jg];
      const float4 wB = sW4[(k4 * 4 + 1) * 16 + jg];
      const float4 wC = sW4[(k4 * 4 + 2) * 16 + jg];
      const float4 wD = sW4[(k4 * 4 + 3) * 16 + jg];
      acc0 = fmaf(hv.x, wA.x, fmaf(hv.y, wB.x, fmaf(hv.z, wC.x, fmaf(hv.w, wD.x, acc0))));
      acc1 = fmaf(hv.x, wA.y, fmaf(hv.y, wB.y, fmaf(hv.z, wC.y, fmaf(hv.w, wD.y, acc1))));
      acc2 = fmaf(hv.x, wA.z, fmaf(hv.y, wB.z, fmaf(hv.z, wC.z, fmaf(hv.w, wD.z, acc2))));
      acc3 = fmaf(hv.x, wA.w, fmaf(hv.y, wB.w, fmaf(hv.z, wC.w, fmaf(hv.w, wD.w, acc3))));
    }
  }

  {
    const float w20 = __ldg(&W2[j0]),     w21 = __ldg(&W2[j0 + 1]);
    const float w22 = __ldg(&W2[j0 + 2]), w23 = __ldg(&W2[j0 + 3]);
    sPart[rg][jg] = fmaxf(acc0, 0.0f) * w20 + fmaxf(acc1, 0.0f) * w21
                  + fmaxf(acc2, 0.0f) * w22 + fmaxf(acc3, 0.0f) * w23;
  }
  __syncthreads();

  if (tid < MLP_ROWS) {
    float s = __ldg(&b2[0]);
    #pragma unroll
    for (int g = 0; g < 16; g++) s += sPart[tid][g];
    const float ev = 1.0f / (1.0f + expf(-s));
    sE[tid] = ev;
    out_e[rowbase + tid] = ev;
  }
  __syncthreads();

  // Emit he16 = e_row * h (h rows L1-hot).
  __half2* he2 = (__half2*)g_he;
  const float4* h4b = (const float4*)(h + (size_t)rowbase * DD);
  #pragma unroll
  for (int i = tid; i < MLP_ROWS * (DD / 4); i += 256) {
    const int r = i >> 6;
    const float4 hv = __ldg(&h4b[i]);
    const float e = sE[r];
    const size_t base = ((size_t)rowbase * DD + i * 4) >> 1;
    he2[base]     = __floats2half2_rn(hv.x * e, hv.y * e);
    he2[base + 1] = __floats2half2_rn(hv.z * e, hv.w * e);
  }
}

// ---------------------------------------------------------------------------
// Kernel 2: h_out[i,:] = sum_{j: A[i,j] > 0} he[j,:]
// One block (256 thr = 8 warps) per output row.
// A row (32 KB) fetched via cp.async.bulk (UBLKCP) -> smem: the A stream
// bypasses the L1tex register-load path entirely, leaving L1tex for the
// gather. Scan runs over smem; gather = 1 warp-LDG.128 per nnz of the fp16
// he row (L2-resident), fp32 accumulate, cross-warp smem reduce.
// ---------------------------------------------------------------------------
__global__ void __launch_bounds__(256) agg_kernel(const float* __restrict__ A,
                                                  float* __restrict__ out) {
  __shared__ __align__(128) uint4 sA[NN / 4];        // 32 KB A row
  __shared__ __align__(8) unsigned long long s_mbar;
  __shared__ unsigned short s_idx[2048];
  __shared__ int s_cnt;
  __shared__ float s_red[8][DD];                     // 8 KB

  const int row = blockIdx.x;
  const int tid = threadIdx.x;
  const int wid = tid >> 5;
  const int lane = tid & 31;

  // mbarrier init + bulk copy issue (single thread).
  unsigned mbar_u32;
  {
    unsigned long long* mb = &s_mbar;
    asm("{ .reg .u64 t; cvta.to.shared.u64 t, %1; cvt.u32.u64 %0, t; }"
        : "=r"(mbar_u32) : "l"(mb));
  }
  unsigned sA_u32;
  {
    asm("{ .reg .u64 t; cvta.to.shared.u64 t, %1; cvt.u32.u64 %0, t; }"
        : "=r"(sA_u32) : "l"(&sA[0]));
  }

  if (tid == 0) {
    s_cnt = 0;
    asm volatile("mbarrier.init.shared.b64 [%0], 1;" :: "r"(mbar_u32) : "memory");
    asm volatile("fence.proxy.async.shared::cta;" ::: "memory");
    asm volatile("mbarrier.arrive.expect_tx.shared.b64 _, [%0], %1;"
                 :: "r"(mbar_u32), "r"(32768) : "memory");
    const float* src = A + (size_t)row * NN;
    asm volatile(
        "cp.async.bulk.shared::cluster.global.mbarrier::complete_tx::bytes "
        "[%0], [%1], %2, [%3];"
        :: "r"(sA_u32), "l"(src), "r"(32768), "r"(mbar_u32) : "memory");
  }
  __syncthreads();

  // Wait for the bulk copy (phase 0).
  {
    unsigned done;
    asm volatile(
        "{\n\t.reg .pred p;\n\t"
        "mbarrier.try_wait.parity.acquire.cta.shared::cta.b64 p, [%1], 0;\n\t"
        "selp.b32 %0, 1, 0, p;\n\t}"
        : "=r"(done) : "r"(mbar_u32) : "memory");
    if (!done) {
      asm volatile(
          "{\n\t.reg .pred P1;\n\t"
          "WL_%=:\n\t"
          "mbarrier.try_wait.parity.acquire.cta.shared::cta.b64 P1, [%0], 0, 0x989680;\n\t"
          "@P1 bra.uni WD_%=;\n\t"
          "bra.uni WL_%=;\n\t"
          "WD_%=:\n\t}"
          :: "r"(mbar_u32) : "memory");
    }
  }

  // Scan smem: a > 0 <=> bit pattern != 0 (values are 0 or positive floats).
  #pragma unroll
  for (int r = 0; r < 8; r++) {
    const int vi = tid + r * 256;
    const uint4 a = sA[vi];
    if (a.x | a.y | a.z | a.w) {
      const int j0 = vi << 2;
      if (a.x) s_idx[atomicAdd(&s_cnt, 1)] = (unsigned short)j0;
      if (a.y) s_idx[atomicAdd(&s_cnt, 1)] = (unsigned short)(j0 + 1);
      if (a.z) s_idx[atomicAdd(&s_cnt, 1)] = (unsigned short)(j0 + 2);
      if (a.w) s_idx[atomicAdd(&s_cnt, 1)] = (unsigned short)(j0 + 3);
    }
  }
  __syncthreads();
  const int cnt = s_cnt;

  // Gather: warp w handles nnz k = w, w+8, ...; full he row per warp-LDG.128.
  const uint4* he4 = (const uint4*)g_he;   // he row = 32 uint4 (256 halves)
  float acc[8] = {0.f, 0.f, 0.f, 0.f, 0.f, 0.f, 0.f, 0.f};

  int k = wid;
  for (; k + 8 < cnt; k += 16) {           // 2-way unrolled for MLP
    const int ja = s_idx[k];
    const int jb = s_idx[k + 8];
    const uint4 va = __ldg(&he4[(size_t)ja * 32 + lane]);
    const uint4 vb = __ldg(&he4[(size_t)jb * 32 + lane]);
    const __half2* pa = (const __half2*)&va;
    const __half2* pb = (const __half2*)&vb;
    #pragma unroll
    for (int q = 0; q < 4; q++) {
      const float2 fa = __half22float2(pa[q]);
      const float2 fb = __half22float2(pb[q]);
      acc[2 * q]     += fa.x + fb.x;
      acc[2 * q + 1] += fa.y + fb.y;
    }
  }
  if (k < cnt) {
    const int j = s_idx[k];
    const uint4 v = __ldg(&he4[(size_t)j * 32 + lane]);
    const __half2* p = (const __half2*)&v;
    #pragma unroll
    for (int q = 0; q < 4; q++) {
      const float2 f = __half22float2(p[q]);
      acc[2 * q]     += f.x;
      acc[2 * q + 1] += f.y;
    }
  }

  // Cross-warp reduce: warp's thread covers cols lane*8 .. +7.
  #pragma unroll
  for (int q = 0; q < 8; q++) s_red[wid][lane * 8 + q] = acc[q];
  __syncthreads();

  float s = 0.0f;
  #pragma unroll
  for (int w = 0; w < 8; w++) s += s_red[w][tid];
  out[(size_t)row * DD + tid] = s;
}

// ---------------------------------------------------------------------------
// Inputs (setup_inputs order):
//   0: graph_info [N*N], 1: h [N*D], 2: W1 [D*H], 3: b1 [H], 4: W2 [H], 5: b2 [1]
// Output: h_out [N*D] followed by e [N].
// ---------------------------------------------------------------------------
extern "C" void kernel_launch(void* const* d_in, const int* in_sizes, int n_in,
                              void* d_out, int out_size) {
  const float* A  = (const float*)d_in[0];
  const float* h  = (const float*)d_in[1];
  const float* W1 = (const float*)d_in[2];
  const float* b1 = (const float*)d_in[3];
  const float* W2 = (const float*)d_in[4];
  const float* b2 = (const float*)d_in[5];

  float* out_h = (float*)d_out;                     // [N*D]
  float* out_e = (float*)d_out + (size_t)NN * DD;   // [N]

  mlp_kernel<<<NN / MLP_ROWS, 256>>>(h, W1, b1, W2, b2, out_e);
  agg_kernel<<<NN, 256>>>(A, out_h);
}

// round 5
// speedup vs baseline: 1.4680x; 1.4680x over previous
#include <cuda_runtime.h>
#include <cuda_fp16.h>
#include <math.h>

#define NN 8192
#define DD 256
#define HH 64

// Pre-scaled features: he[j, d] = e_j * h[j, d], fp16 (4 MB, L2-resident).
__device__ __half g_he[NN * DD];

// ---------------------------------------------------------------------------
// Kernel 1: e = sigmoid(relu(h @ W1 + b1) @ W2 + b2); emit he = e*h (fp16).
// 32 rows/block (256 blocks), 256 thr: j = tid&63, rg = tid>>6 owns 8 rows.
// h staged in smem (broadcast LDS); W1 read UNtransposed: 4 coalesced scalar
// LDG.32 per k4 (lane = j -> 128B lines, L1-resident 64 KB).
// ---------------------------------------------------------------------------
#define MLP_ROWS 32
__global__ void __launch_bounds__(256) mlp_kernel(
    const float* __restrict__ h, const float* __restrict__ W1,
    const float* __restrict__ b1, const float* __restrict__ W2,
    const float* __restrict__ b2, float* __restrict__ out_e) {

  __shared__ float sh_h[MLP_ROWS * DD];     // 32 KB
  __shared__ float sT[MLP_ROWS][HH + 1];    // relu*W2 partials
  __shared__ float sE[MLP_ROWS];

  const int tid = threadIdx.x;
  const int rowbase = blockIdx.x * MLP_ROWS;

  // Stage 32 h rows, coalesced float4.
  {
    const float4* src = (const float4*)(h + (size_t)rowbase * DD);
    float4* dst = (float4*)sh_h;
    #pragma unroll
    for (int i = tid; i < MLP_ROWS * DD / 4; i += 256) dst[i] = __ldg(&src[i]);
  }
  __syncthreads();

  const int j  = tid & 63;
  const int rg = tid >> 6;                  // 0..3, 8 rows each

  float acc[8];
  const float bj = __ldg(&b1[j]);
  #pragma unroll
  for (int r = 0; r < 8; r++) acc[r] = bj;

  const float4* sh4 = (const float4*)sh_h;

  #pragma unroll 4
  for (int k4 = 0; k4 < DD / 4; k4++) {
    // W1 rows k4*4..+3, column j: coalesced over lanes (j consecutive).
    const float w0 = __ldg(&W1[(k4 * 4 + 0) * HH + j]);
    const float w1 = __ldg(&W1[(k4 * 4 + 1) * HH + j]);
    const float w2 = __ldg(&W1[(k4 * 4 + 2) * HH + j]);
    const float w3 = __ldg(&W1[(k4 * 4 + 3) * HH + j]);
    #pragma unroll
    for (int r = 0; r < 8; r++) {
      const float4 hv = sh4[(rg * 8 + r) * (DD / 4) + k4];  // broadcast
      acc[r] = fmaf(hv.x, w0, fmaf(hv.y, w1, fmaf(hv.z, w2, fmaf(hv.w, w3, acc[r]))));
    }
  }

  {
    const float w2j = __ldg(&W2[j]);
    #pragma unroll
    for (int r = 0; r < 8; r++)
      sT[rg * 8 + r][j] = fmaxf(acc[r], 0.0f) * w2j;
  }
  __syncthreads();

  if (tid < MLP_ROWS) {
    float s = __ldg(&b2[0]);
    #pragma unroll
    for (int jj = 0; jj < HH; jj++) s += sT[tid][jj];
    const float ev = 1.0f / (1.0f + expf(-s));
    sE[tid] = ev;
    out_e[rowbase + tid] = ev;
  }
  __syncthreads();

  // Emit he16 = e_row * h from smem.
  __half2* he2 = (__half2*)g_he;
  #pragma unroll
  for (int i = tid; i < MLP_ROWS * (DD / 4); i += 256) {
    const int r = i >> 6;
    const float4 hv = ((const float4*)sh_h)[i];
    const float e = sE[r];
    const size_t base = ((size_t)rowbase * DD + i * 4) >> 1;
    he2[base]     = __floats2half2_rn(hv.x * e, hv.y * e);
    he2[base + 1] = __floats2half2_rn(hv.z * e, hv.w * e);
  }
}

// ---------------------------------------------------------------------------
// Kernel 2: h_out[i,:] = sum_{j: A[i,j] > 0} he[j,:]
// One block (8 warps) per row; each warp fully independent on its 1/8 slice:
//   scan: 8 front-batched __ldcs uint4 -> 32-bit register pending mask
//         (no atomics, no smem, no ballots-per-element)
//   gather: per round, 1 ballot picks up to 4 source lanes; shfl their j's;
//           4 independent warp-LDG.128 of fp16 he rows (MLP=4); owners clear.
// Single __syncthreads per row (cross-warp reduce).
// ---------------------------------------------------------------------------
__global__ void __launch_bounds__(256) agg_kernel(const float* __restrict__ A,
                                                  float* __restrict__ out) {
  __shared__ float s_red[8][DD];            // 8 KB

  const int row = blockIdx.x;
  const int tid = threadIdx.x;
  const int wid = tid >> 5;
  const int lane = tid & 31;

  // Warp slice: 256 uint4 = 1024 columns starting at wid*1024.
  const uint4* Aslice = (const uint4*)(A + (size_t)row * NN) + wid * 256;

  // Front-batch all 8 streaming loads (DRAM MLP = 8).
  uint4 av[8];
  #pragma unroll
  for (int r = 0; r < 8; r++)
    av[r] = __ldcs(Aslice + r * 32 + lane);

  // pending bit (r*4 + c) = A[wid*1024 + (r*32+lane)*4 + c] > 0.
  // a > 0 <=> bit pattern != 0 (values are +0 or positive floats).
  unsigned pending = 0u;
  #pragma unroll
  for (int r = 0; r < 8; r++) {
    unsigned f = 0u;
    if (av[r].x) f |= 1u;
    if (av[r].y) f |= 2u;
    if (av[r].z) f |= 4u;
    if (av[r].w) f |= 8u;
    pending |= f << (r * 4);
  }

  // Gather: he row = 32 uint4 (256 fp16), one warp-LDG.128 per nnz.
  const uint4* he4 = (const uint4*)g_he;
  float acc[8] = {0.f, 0.f, 0.f, 0.f, 0.f, 0.f, 0.f, 0.f};

  while (true) {
    unsigned m = __ballot_sync(0xFFFFFFFFu, pending != 0u);
    if (!m) break;

    // My candidate column (lowest pending bit): j = base + r*128 + lane*4 + c.
    const int b = __ffs(pending) - 1;       // -1 if none (unused then)
    const int jmine = wid * 1024 + ((b & ~3) << 5) + (lane << 2) + (b & 3);

    const int n = __popc(m) < 4 ? __popc(m) : 4;
    int s0 = __ffs(m) - 1;            m &= m - 1;
    int s1 = m ? __ffs(m) - 1 : s0;   m &= m - 1;
    int s2 = m ? __ffs(m) - 1 : s0;   m &= m - 1;
    int s3 = m ? __ffs(m) - 1 : s0;

    const int j0 = __shfl_sync(0xFFFFFFFFu, jmine, s0);
    const int j1 = __shfl_sync(0xFFFFFFFFu, jmine, s1);
    const int j2 = __shfl_sync(0xFFFFFFFFu, jmine, s2);
    const int j3 = __shfl_sync(0xFFFFFFFFu, jmine, s3);

    // Each selected source lane retires its lowest bit.
    if (lane == s0 || (n > 1 && lane == s1) || (n > 2 && lane == s2) ||
        (n > 3 && lane == s3))
      pending &= pending - 1u;

    // Issue up to 4 independent row loads (uniform branches -> MLP 4).
    uint4 v0, v1, v2, v3;
    v0 = __ldg(&he4[(size_t)j0 * 32 + lane]);
    if (n > 1) v1 = __ldg(&he4[(size_t)j1 * 32 + lane]);
    if (n > 2) v2 = __ldg(&he4[(size_t)j2 * 32 + lane]);
    if (n > 3) v3 = __ldg(&he4[(size_t)j3 * 32 + lane]);

    {
      const __half2* p = (const __half2*)&v0;
      #pragma unroll
      for (int q = 0; q < 4; q++) {
        const float2 f = __half22float2(p[q]);
        acc[2 * q] += f.x; acc[2 * q + 1] += f.y;
      }
    }
    if (n > 1) {
      const __half2* p = (const __half2*)&v1;
      #pragma unroll
      for (int q = 0; q < 4; q++) {
        const float2 f = __half22float2(p[q]);
        acc[2 * q] += f.x; acc[2 * q + 1] += f.y;
      }
    }
    if (n > 2) {
      const __half2* p = (const __half2*)&v2;
      #pragma unroll
      for (int q = 0; q < 4; q++) {
        const float2 f = __half22float2(p[q]);
        acc[2 * q] += f.x; acc[2 * q + 1] += f.y;
      }
    }
    if (n > 3) {
      const __half2* p = (const __half2*)&v3;
      #pragma unroll
      for (int q = 0; q < 4; q++) {
        const float2 f = __half22float2(p[q]);
        acc[2 * q] += f.x; acc[2 * q + 1] += f.y;
      }
    }
  }

  // Cross-warp reduce. acc[q] = column lane*8 + q. float4 stores.
  {
    float4* rr = (float4*)s_red[wid];
    rr[lane * 2]     = make_float4(acc[0], acc[1], acc[2], acc[3]);
    rr[lane * 2 + 1] = make_float4(acc[4], acc[5], acc[6], acc[7]);
  }
  __syncthreads();

  float s = 0.0f;
  #pragma unroll
  for (int w = 0; w < 8; w++) s += s_red[w][tid];
  out[(size_t)row * DD + tid] = s;
}

// ---------------------------------------------------------------------------
// Inputs (setup_inputs order):
//   0: graph_info [N*N], 1: h [N*D], 2: W1 [D*H], 3: b1 [H], 4: W2 [H], 5: b2 [1]
// Output: h_out [N*D] followed by e [N].
// ---------------------------------------------------------------------------
extern "C" void kernel_launch(void* const* d_in, const int* in_sizes, int n_in,
                              void* d_out, int out_size) {
  const float* A  = (const float*)d_in[0];
  const float* h  = (const float*)d_in[1];
  const float* W1 = (const float*)d_in[2];
  const float* b1 = (const float*)d_in[3];
  const float* W2 = (const float*)d_in[4];
  const float* b2 = (const float*)d_in[5];

  float* out_h = (float*)d_out;                     // [N*D]
  float* out_e = (float*)d_out + (size_t)NN * DD;   // [N]

  mlp_kernel<<<NN / MLP_ROWS, 256>>>(h, W1, b1, W2, b2, out_e);
  agg_kernel<<<NN, 256>>>(A, out_h);
}